// round 13
// baseline (speedup 1.0000x reference)
#include <cuda_runtime.h>
#include <cuda_fp16.h>
#include <cstdint>

// vaeVectorQuantizer: x[N=131072, D=64], E[D=64, K=1024]
// Single fp16-product approx GEMM (mma.sync.m16n8k16.f16) for candidate ranking
// + per-row (best, secondVal) gap test + exact fp32 full-row rescan (reference
// rounding) for rows with gap < EPS. y_sq/e_sq correctly rounded via double.

#define D_DIM 64
#define K_DIM 1024
#define ROWS_PER_CTA 128
#define NTILE 128
#define NTILES 8
#define MTHREADS 512
#define PTHREADS 256
#define EPS 1e-2f

#define PADROW 144
#define SM_X     0                         // 128 * 144 = 18432 (h1 limb only)
#define SM_B     18432
#define B_BYTES  (NTILE * 64 * 2)          // 16384 per tile (fragment-packed h1)
#define SM_ESQ   (SM_B + 2 * B_BYTES)      // 51200
#define SM_YS    (SM_ESQ + 4096)           // 55296
#define SM_MRG   (SM_YS + 512)             // 55808: qv[4][128], qv2[4][128], qc[4][128]
#define SM_CIDX  (SM_MRG + 6144)           // 61952
#define SM_XROW  (SM_CIDX + 512)           // 62464 (one x row, 256B)
#define SM_LIST  (SM_XROW + 256)           // 62720 (flagged rows, 128 ints)
#define SM_CNT   (SM_LIST + 512)           // 63232
#define SM_WRED  (SM_CNT + 16)             // 63248: 16*(float+int)=128
#define SM_TOTAL 63392

__device__ float g_esq[K_DIM];
__device__ float g_ET[K_DIM * D_DIM];          // [k][d] fp32: gather + rescan
__device__ uint2 g_Bf[NTILES * 4 * 16 * 32];   // [t][kc][nf][lane] h1 fragments

__device__ __forceinline__ uint32_t smem_u32(const void* p) {
    uint32_t a;
    asm("{ .reg .u64 t; cvta.to.shared.u64 t, %1; cvt.u32.u64 %0, t; }" : "=r"(a) : "l"(p));
    return a;
}
__device__ __forceinline__ void cp16(uint32_t dst, const void* src) {
    asm volatile("cp.async.cg.shared.global [%0], [%1], 16;" :: "r"(dst), "l"(src));
}
#define CP_COMMIT() asm volatile("cp.async.commit_group;" ::: "memory")
#define CP_WAIT(N)  asm volatile("cp.async.wait_group %0;" :: "n"(N) : "memory")

__device__ __forceinline__ void mma16816h(float* c, uint32_t a0, uint32_t a1,
                                          uint32_t a2, uint32_t a3,
                                          uint32_t b0, uint32_t b1) {
    asm volatile(
        "mma.sync.aligned.m16n8k16.row.col.f32.f16.f16.f32 "
        "{%0,%1,%2,%3}, {%4,%5,%6,%7}, {%8,%9}, {%0,%1,%2,%3};"
        : "+f"(c[0]), "+f"(c[1]), "+f"(c[2]), "+f"(c[3])
        : "r"(a0), "r"(a1), "r"(a2), "r"(a3), "r"(b0), "r"(b1));
}

// approx top-1 + second-best value (no second index needed)
__device__ __forceinline__ void upd(float k, int cb, float& v1, int& c1, float& v2) {
    bool p = k < v1;
    v2 = p ? v1 : fminf(v2, k);
    c1 = p ? cb : c1;
    v1 = p ? k : v1;
}
// merge two (v1,c1,v2) candidate sets
__device__ __forceinline__ void mrg(float ov1, int oc1, float ov2,
                                    float& v1, int& c1, float& v2) {
    float loser = fmaxf(v1, ov1);
    v2 = fminf(fminf(v2, ov2), loser);
    bool p = ov1 < v1;
    v1 = p ? ov1 : v1;
    c1 = p ? oc1 : c1;
}

// ---------------- prep: e_sq (double) + transposed gather table ----------------
__global__ void vq_prep(const float* __restrict__ E) {
    int wid = threadIdx.x >> 5, lane = threadIdx.x & 31;
    int k = blockIdx.x * 8 + wid;
    float v0 = E[lane * K_DIM + k];
    float v1 = E[(lane + 32) * K_DIM + k];
    g_ET[k * D_DIM + lane]      = v0;
    g_ET[k * D_DIM + lane + 32] = v1;
    double s = fma((double)v0, (double)v0, (double)v1 * (double)v1);
#pragma unroll
    for (int off = 16; off >= 1; off >>= 1)
        s += __shfl_xor_sync(0xffffffffu, s, off);
    if (lane == 0) g_esq[k] = (float)s;
}

// ---------------- prep: B h1 fragments in mma lane order ----------------
// Entry (t,kc,nf,lane), reg m, half j: E_h1[d][code],
//   d = kc*16 + (lane%4)*2 + m*8 + j, code = t*128 + nf*8 + lane/4
__global__ void vq_prep_b(const float* __restrict__ E) {
    int idx = blockIdx.x * blockDim.x + threadIdx.x;   // 16384 total
    int lane = idx & 31;
    int x1 = idx >> 5;
    int nf = x1 & 15;
    int x2 = x1 >> 4;
    int kc = x2 & 3;
    int t = x2 >> 2;

    int code = t * 128 + nf * 8 + (lane >> 2);
    int c = lane & 3;
    uint32_t r[2];
#pragma unroll
    for (int m = 0; m < 2; ++m) {
        int d0 = kc * 16 + c * 2 + m * 8;
        __half2 pk = __halves2half2(__float2half_rn(E[d0 * K_DIM + code]),
                                    __float2half_rn(E[(d0 + 1) * K_DIM + code]));
        r[m] = *(uint32_t*)&pk;
    }
    g_Bf[idx] = make_uint2(r[0], r[1]);
}

// ---------------- main ----------------
__global__ __launch_bounds__(MTHREADS)
void vq_tc(const float* __restrict__ x, float* __restrict__ out) {
    extern __shared__ __align__(16) char smem[];
    const int tid = threadIdx.x;
    const int wid = tid >> 5;
    const int lane = tid & 31;
    const size_t rowbase = (size_t)blockIdx.x * ROWS_PER_CTA;

    float* esq_s = (float*)(smem + SM_ESQ);
    float* ys_sh = (float*)(smem + SM_YS);
    int*   cidx  = (int*)(smem + SM_CIDX);
    const uint32_t sB_u32 = smem_u32(smem + SM_B);

    *(float2*)(esq_s + 2 * tid) = *(const float2*)(g_esq + 2 * tid);
    if (tid == 0) *(int*)(smem + SM_CNT) = 0;

    // ---- prefetch B tile 0
    {
        const char* src = (const char*)g_Bf;
#pragma unroll
        for (int i = 0; i < 2; ++i)
            cp16(sB_u32 + i * 8192 + tid * 16, src + i * 8192 + tid * 16);
        CP_COMMIT();
    }

    // ---- x: h1 fp16 into padded smem + exact double row norms
    {
        int r = tid >> 2, dq = (tid & 3) * 16;
        const float* xr = x + (rowbase + r) * D_DIM + dq;
        char* xs = smem + SM_X + r * PADROW;
        double s = 0.0;
#pragma unroll
        for (int i = 0; i < 4; ++i) {
            float4 v = *(const float4*)(xr + 4 * i);
            int d0 = dq + 4 * i;
            s = fma((double)v.x, (double)v.x, s);
            s = fma((double)v.y, (double)v.y, s);
            s = fma((double)v.z, (double)v.z, s);
            s = fma((double)v.w, (double)v.w, s);
            *(__half2*)(xs + d0 * 2)     = __halves2half2(__float2half_rn(v.x), __float2half_rn(v.y));
            *(__half2*)(xs + d0 * 2 + 4) = __halves2half2(__float2half_rn(v.z), __float2half_rn(v.w));
        }
        s += __shfl_xor_sync(0xffffffffu, s, 1);
        s += __shfl_xor_sync(0xffffffffu, s, 2);
        if ((tid & 3) == 0) ys_sh[r] = (float)s;
    }

    const int cq = wid >> 2;           // column quarter (32 codes)
    const int wg = wid & 3;            // row group (32 rows)
    const int g = lane >> 2, c = lane & 3;

    __syncthreads();

    float ysr[2][2];
    const char* aRow[2][2];
#pragma unroll
    for (int mf = 0; mf < 2; ++mf)
#pragma unroll
        for (int h = 0; h < 2; ++h) {
            int r = wg * 32 + mf * 16 + h * 8 + g;
            ysr[mf][h] = ys_sh[r];
            aRow[mf][h] = smem + SM_X + r * PADROW + c * 4;
        }

    float v1[2][2] = {{3.402823466e38f, 3.402823466e38f},
                      {3.402823466e38f, 3.402823466e38f}};
    float v2[2][2] = {{3.402823466e38f, 3.402823466e38f},
                      {3.402823466e38f, 3.402823466e38f}};
    int   c1[2][2] = {{0, 0}, {0, 0}};

    for (int t = 0; t < NTILES; ++t) {
        const int buf = t & 1;
        if (t + 1 < NTILES) {
            const char* src = (const char*)g_Bf + (t + 1) * B_BYTES;
            uint32_t dst = sB_u32 + (buf ^ 1) * B_BYTES;
#pragma unroll
            for (int i = 0; i < 2; ++i)
                cp16(dst + i * 8192 + tid * 16, src + i * 8192 + tid * 16);
            CP_COMMIT();
            CP_WAIT(1);
        } else {
            CP_WAIT(0);
        }
        __syncthreads();

        float acc[4][2][4];
#pragma unroll
        for (int nf = 0; nf < 4; ++nf)
#pragma unroll
            for (int mf = 0; mf < 2; ++mf)
#pragma unroll
                for (int j = 0; j < 4; ++j) acc[nf][mf][j] = 0.f;

#pragma unroll
        for (int kc = 0; kc < 4; ++kc) {
            uint32_t A[2][4];
#pragma unroll
            for (int mf = 0; mf < 2; ++mf) {
                const char* a0p = aRow[mf][0] + kc * 32;
                const char* a1p = aRow[mf][1] + kc * 32;
                A[mf][0] = *(const uint32_t*)(a0p);
                A[mf][1] = *(const uint32_t*)(a1p);
                A[mf][2] = *(const uint32_t*)(a0p + 16);
                A[mf][3] = *(const uint32_t*)(a1p + 16);
            }
            const uint2* bp = (const uint2*)(smem + SM_B + buf * B_BYTES + kc * 4096)
                              + cq * 128 + lane;
            uint2 B[4];
#pragma unroll
            for (int nf = 0; nf < 4; ++nf) B[nf] = bp[nf * 32];
#pragma unroll
            for (int mf = 0; mf < 2; ++mf)
#pragma unroll
                for (int nf = 0; nf < 4; ++nf)
                    mma16816h(acc[nf][mf], A[mf][0], A[mf][1], A[mf][2], A[mf][3],
                              B[nf].x, B[nf].y);
        }

        // ---- approx argmin epilogue with second-best value tracking
#pragma unroll
        for (int nf = 0; nf < 4; ++nf) {
            int cb = t * NTILE + cq * 32 + nf * 8 + 2 * c;
            float e0 = esq_s[cb], e1 = esq_s[cb + 1];
#pragma unroll
            for (int mf = 0; mf < 2; ++mf) {
                float k00 = fmaf(-2.f, acc[nf][mf][0], __fadd_rn(ysr[mf][0], e0));
                float k01 = fmaf(-2.f, acc[nf][mf][1], __fadd_rn(ysr[mf][0], e1));
                float k10 = fmaf(-2.f, acc[nf][mf][2], __fadd_rn(ysr[mf][1], e0));
                float k11 = fmaf(-2.f, acc[nf][mf][3], __fadd_rn(ysr[mf][1], e1));
                upd(k00, cb,     v1[mf][0], c1[mf][0], v2[mf][0]);
                upd(k01, cb + 1, v1[mf][0], c1[mf][0], v2[mf][0]);
                upd(k10, cb,     v1[mf][1], c1[mf][1], v2[mf][1]);
                upd(k11, cb + 1, v1[mf][1], c1[mf][1], v2[mf][1]);
            }
        }
        __syncthreads();
    }

    // ---- merge across the 4 lanes (c) sharing each row
#pragma unroll
    for (int off = 1; off <= 2; off <<= 1) {
#pragma unroll
        for (int mf = 0; mf < 2; ++mf)
#pragma unroll
            for (int h = 0; h < 2; ++h) {
                float ov1 = __shfl_xor_sync(0xffffffffu, v1[mf][h], off);
                int   oc1 = __shfl_xor_sync(0xffffffffu, c1[mf][h], off);
                float ov2 = __shfl_xor_sync(0xffffffffu, v2[mf][h], off);
                mrg(ov1, oc1, ov2, v1[mf][h], c1[mf][h], v2[mf][h]);
            }
    }
    // ---- publish per-quarter (v1,c1,v2), merge across quarters
    float* qv  = (float*)(smem + SM_MRG);          // [cq][row]
    float* qv2 = (float*)(smem + SM_MRG + 2048);
    int*   qc  = (int*)(smem + SM_MRG + 4096);
    if (c == 0) {
#pragma unroll
        for (int mf = 0; mf < 2; ++mf)
#pragma unroll
            for (int h = 0; h < 2; ++h) {
                int r = cq * 128 + wg * 32 + mf * 16 + h * 8 + g;
                qv[r] = v1[mf][h]; qv2[r] = v2[mf][h]; qc[r] = c1[mf][h];
            }
    }
    __syncthreads();
    int* list = (int*)(smem + SM_LIST);
    int* cnt  = (int*)(smem + SM_CNT);
    if (tid < ROWS_PER_CTA) {
        float V1 = qv[tid], V2 = qv2[tid];
        int C = qc[tid];
#pragma unroll
        for (int q = 1; q < 4; ++q) {
            float o1 = qv[q * 128 + tid], o2 = qv2[q * 128 + tid];
            int oc = qc[q * 128 + tid];
            float loser = fmaxf(V1, o1);
            V2 = fminf(fminf(V2, o2), loser);
            bool p = o1 < V1;
            V1 = p ? o1 : V1;
            C = p ? oc : C;
        }
        cidx[tid] = C;
        if (V2 - V1 < EPS) {           // ambiguous under approx error -> exact rescan
            int slot = atomicAdd(cnt, 1);
            list[slot] = tid;
        }
    }
    __syncthreads();

    // ---- exact fp32 rescan of flagged rows (reference rounding, tie->lowest)
    const int nflag = *cnt;
    float* xrow = (float*)(smem + SM_XROW);
    float* wrv  = (float*)(smem + SM_WRED);
    int*   wrc  = (int*)(smem + SM_WRED + 64);
    for (int i = 0; i < nflag; ++i) {
        int r = list[i];
        if (tid < 16)
            ((float4*)xrow)[tid] = ((const float4*)(x + (rowbase + r) * D_DIM))[tid];
        __syncthreads();
        float ys = ys_sh[r];
        float bestv = 3.402823466e38f;
        int   bestc = 0;
#pragma unroll
        for (int kk = 0; kk < 2; ++kk) {
            int k = 2 * tid + kk;
            const float* ek = g_ET + k * D_DIM;
            float dot = 0.f;
#pragma unroll
            for (int d = 0; d < D_DIM; ++d) dot = fmaf(xrow[d], ek[d], dot);
            float key = fmaf(-2.f, dot, __fadd_rn(ys, esq_s[k]));
            if (key < bestv || (key == bestv && k < bestc)) { bestv = key; bestc = k; }
        }
#pragma unroll
        for (int off = 16; off >= 1; off >>= 1) {
            float ov = __shfl_xor_sync(0xffffffffu, bestv, off);
            int   oc = __shfl_xor_sync(0xffffffffu, bestc, off);
            if (ov < bestv || (ov == bestv && oc < bestc)) { bestv = ov; bestc = oc; }
        }
        if (lane == 0) { wrv[wid] = bestv; wrc[wid] = bestc; }
        __syncthreads();
        if (tid == 0) {
            float bv = wrv[0]; int bcn = wrc[0];
#pragma unroll
            for (int w = 1; w < 16; ++w) {
                float v = wrv[w]; int cc = wrc[w];
                if (v < bv || (v == bv && cc < bcn)) { bv = v; bcn = cc; }
            }
            cidx[r] = bcn;
        }
        __syncthreads();
    }

    // ---- gather output rows from transposed codebook
    float* og = out + rowbase * D_DIM;
#pragma unroll
    for (int it = 0; it < 4; ++it) {
        int i  = tid + it * MTHREADS;
        int r  = i >> 4;
        int d0 = (i & 15) << 2;
        *(float4*)(og + r * D_DIM + d0) = *(const float4*)(g_ET + cidx[r] * D_DIM + d0);
    }
}

extern "C" void kernel_launch(void* const* d_in, const int* in_sizes, int n_in,
                              void* d_out, int out_size) {
    const float* x = (const float*)d_in[0];
    const float* E = (const float*)d_in[1];
    float* out = (float*)d_out;
    int N = in_sizes[0] / D_DIM;  // 131072

    cudaFuncSetAttribute(vq_tc, cudaFuncAttributeMaxDynamicSharedMemorySize, SM_TOTAL);
    vq_prep<<<K_DIM / 8, PTHREADS>>>(E);
    vq_prep_b<<<(NTILES * 4 * 16 * 32) / PTHREADS, PTHREADS>>>(E);
    vq_tc<<<N / ROWS_PER_CTA, MTHREADS, SM_TOTAL>>>(x, out);
}

// round 14
// speedup vs baseline: 4.7532x; 4.7532x over previous
#include <cuda_runtime.h>
#include <cuda_fp16.h>
#include <cstdint>

// vaeVectorQuantizer: x[N=131072, D=64], E[D=64, K=1024]
// Single fp16-product approx GEMM (mma.sync.m16n8k16.f16) for candidate ranking
// + per-row (best, secondVal) gap test + exact fp32 full-row rescan (reference
// rounding) for rows with gap < EPS. Rescan reads E in ORIGINAL d-major layout
// with lane-consecutive codes => fully coalesced (R12's 5x regression was
// code-major scattered reads, 32 wavefronts/LDG).

#define D_DIM 64
#define K_DIM 1024
#define ROWS_PER_CTA 128
#define NTILE 128
#define NTILES 8
#define MTHREADS 512
#define PTHREADS 256
#define EPS 1e-2f

#define PADROW 144
#define SM_X     0                         // 128 * 144 = 18432 (h1 limb only)
#define SM_B     18432
#define B_BYTES  (NTILE * 64 * 2)          // 16384 per tile (fragment-packed h1)
#define SM_ESQ   (SM_B + 2 * B_BYTES)      // 51200
#define SM_YS    (SM_ESQ + 4096)           // 55296
#define SM_MRG   (SM_YS + 512)             // 55808: qv[4][128], qv2[4][128], qc[4][128]
#define SM_CIDX  (SM_MRG + 6144)           // 61952
#define SM_XROW  (SM_CIDX + 512)           // 62464 (one x row, 256B)
#define SM_LIST  (SM_XROW + 256)           // 62720 (flagged rows, 128 ints)
#define SM_CNT   (SM_LIST + 512)           // 63232
#define SM_WRED  (SM_CNT + 16)             // 63248: 16*(float+int)=128
#define SM_TOTAL 63392

__device__ float g_esq[K_DIM];
__device__ float g_ET[K_DIM * D_DIM];          // [k][d] fp32: gather only
__device__ uint2 g_Bf[NTILES * 4 * 16 * 32];   // [t][kc][nf][lane] h1 fragments

__device__ __forceinline__ uint32_t smem_u32(const void* p) {
    uint32_t a;
    asm("{ .reg .u64 t; cvta.to.shared.u64 t, %1; cvt.u32.u64 %0, t; }" : "=r"(a) : "l"(p));
    return a;
}
__device__ __forceinline__ void cp16(uint32_t dst, const void* src) {
    asm volatile("cp.async.cg.shared.global [%0], [%1], 16;" :: "r"(dst), "l"(src));
}
#define CP_COMMIT() asm volatile("cp.async.commit_group;" ::: "memory")
#define CP_WAIT(N)  asm volatile("cp.async.wait_group %0;" :: "n"(N) : "memory")

__device__ __forceinline__ void mma16816h(float* c, uint32_t a0, uint32_t a1,
                                          uint32_t a2, uint32_t a3,
                                          uint32_t b0, uint32_t b1) {
    asm volatile(
        "mma.sync.aligned.m16n8k16.row.col.f32.f16.f16.f32 "
        "{%0,%1,%2,%3}, {%4,%5,%6,%7}, {%8,%9}, {%0,%1,%2,%3};"
        : "+f"(c[0]), "+f"(c[1]), "+f"(c[2]), "+f"(c[3])
        : "r"(a0), "r"(a1), "r"(a2), "r"(a3), "r"(b0), "r"(b1));
}

// approx top-1 + second-best value (no second index needed)
__device__ __forceinline__ void upd(float k, int cb, float& v1, int& c1, float& v2) {
    bool p = k < v1;
    v2 = p ? v1 : fminf(v2, k);
    c1 = p ? cb : c1;
    v1 = p ? k : v1;
}
__device__ __forceinline__ void mrg(float ov1, int oc1, float ov2,
                                    float& v1, int& c1, float& v2) {
    float loser = fmaxf(v1, ov1);
    v2 = fminf(fminf(v2, ov2), loser);
    bool p = ov1 < v1;
    v1 = p ? ov1 : v1;
    c1 = p ? oc1 : c1;
}

// ---------------- prep: e_sq (double) + transposed gather table ----------------
__global__ void vq_prep(const float* __restrict__ E) {
    int wid = threadIdx.x >> 5, lane = threadIdx.x & 31;
    int k = blockIdx.x * 8 + wid;
    float v0 = E[lane * K_DIM + k];
    float v1 = E[(lane + 32) * K_DIM + k];
    g_ET[k * D_DIM + lane]      = v0;
    g_ET[k * D_DIM + lane + 32] = v1;
    double s = fma((double)v0, (double)v0, (double)v1 * (double)v1);
#pragma unroll
    for (int off = 16; off >= 1; off >>= 1)
        s += __shfl_xor_sync(0xffffffffu, s, off);
    if (lane == 0) g_esq[k] = (float)s;
}

// ---------------- prep: B h1 fragments in mma lane order ----------------
__global__ void vq_prep_b(const float* __restrict__ E) {
    int idx = blockIdx.x * blockDim.x + threadIdx.x;   // 16384 total
    int lane = idx & 31;
    int x1 = idx >> 5;
    int nf = x1 & 15;
    int x2 = x1 >> 4;
    int kc = x2 & 3;
    int t = x2 >> 2;

    int code = t * 128 + nf * 8 + (lane >> 2);
    int c = lane & 3;
    uint32_t r[2];
#pragma unroll
    for (int m = 0; m < 2; ++m) {
        int d0 = kc * 16 + c * 2 + m * 8;
        __half2 pk = __halves2half2(__float2half_rn(E[d0 * K_DIM + code]),
                                    __float2half_rn(E[(d0 + 1) * K_DIM + code]));
        r[m] = *(uint32_t*)&pk;
    }
    g_Bf[idx] = make_uint2(r[0], r[1]);
}

// ---------------- main ----------------
__global__ __launch_bounds__(MTHREADS)
void vq_tc(const float* __restrict__ x, const float* __restrict__ E,
           float* __restrict__ out) {
    extern __shared__ __align__(16) char smem[];
    const int tid = threadIdx.x;
    const int wid = tid >> 5;
    const int lane = tid & 31;
    const size_t rowbase = (size_t)blockIdx.x * ROWS_PER_CTA;

    float* esq_s = (float*)(smem + SM_ESQ);
    float* ys_sh = (float*)(smem + SM_YS);
    int*   cidx  = (int*)(smem + SM_CIDX);
    const uint32_t sB_u32 = smem_u32(smem + SM_B);

    *(float2*)(esq_s + 2 * tid) = *(const float2*)(g_esq + 2 * tid);
    if (tid == 0) *(int*)(smem + SM_CNT) = 0;

    // ---- prefetch B tile 0
    {
        const char* src = (const char*)g_Bf;
#pragma unroll
        for (int i = 0; i < 2; ++i)
            cp16(sB_u32 + i * 8192 + tid * 16, src + i * 8192 + tid * 16);
        CP_COMMIT();
    }

    // ---- x: h1 fp16 into padded smem + exact double row norms
    {
        int r = tid >> 2, dq = (tid & 3) * 16;
        const float* xr = x + (rowbase + r) * D_DIM + dq;
        char* xs = smem + SM_X + r * PADROW;
        double s = 0.0;
#pragma unroll
        for (int i = 0; i < 4; ++i) {
            float4 v = *(const float4*)(xr + 4 * i);
            int d0 = dq + 4 * i;
            s = fma((double)v.x, (double)v.x, s);
            s = fma((double)v.y, (double)v.y, s);
            s = fma((double)v.z, (double)v.z, s);
            s = fma((double)v.w, (double)v.w, s);
            *(__half2*)(xs + d0 * 2)     = __halves2half2(__float2half_rn(v.x), __float2half_rn(v.y));
            *(__half2*)(xs + d0 * 2 + 4) = __halves2half2(__float2half_rn(v.z), __float2half_rn(v.w));
        }
        s += __shfl_xor_sync(0xffffffffu, s, 1);
        s += __shfl_xor_sync(0xffffffffu, s, 2);
        if ((tid & 3) == 0) ys_sh[r] = (float)s;
    }

    const int cq = wid >> 2;           // column quarter (32 codes)
    const int wg = wid & 3;            // row group (32 rows)
    const int g = lane >> 2, c = lane & 3;

    __syncthreads();

    float ysr[2][2];
    const char* aRow[2][2];
#pragma unroll
    for (int mf = 0; mf < 2; ++mf)
#pragma unroll
        for (int h = 0; h < 2; ++h) {
            int r = wg * 32 + mf * 16 + h * 8 + g;
            ysr[mf][h] = ys_sh[r];
            aRow[mf][h] = smem + SM_X + r * PADROW + c * 4;
        }

    float v1[2][2] = {{3.402823466e38f, 3.402823466e38f},
                      {3.402823466e38f, 3.402823466e38f}};
    float v2[2][2] = {{3.402823466e38f, 3.402823466e38f},
                      {3.402823466e38f, 3.402823466e38f}};
    int   c1[2][2] = {{0, 0}, {0, 0}};

    for (int t = 0; t < NTILES; ++t) {
        const int buf = t & 1;
        if (t + 1 < NTILES) {
            const char* src = (const char*)g_Bf + (t + 1) * B_BYTES;
            uint32_t dst = sB_u32 + (buf ^ 1) * B_BYTES;
#pragma unroll
            for (int i = 0; i < 2; ++i)
                cp16(dst + i * 8192 + tid * 16, src + i * 8192 + tid * 16);
            CP_COMMIT();
            CP_WAIT(1);
        } else {
            CP_WAIT(0);
        }
        __syncthreads();

        float acc[4][2][4];
#pragma unroll
        for (int nf = 0; nf < 4; ++nf)
#pragma unroll
            for (int mf = 0; mf < 2; ++mf)
#pragma unroll
                for (int j = 0; j < 4; ++j) acc[nf][mf][j] = 0.f;

#pragma unroll
        for (int kc = 0; kc < 4; ++kc) {
            uint32_t A[2][4];
#pragma unroll
            for (int mf = 0; mf < 2; ++mf) {
                const char* a0p = aRow[mf][0] + kc * 32;
                const char* a1p = aRow[mf][1] + kc * 32;
                A[mf][0] = *(const uint32_t*)(a0p);
                A[mf][1] = *(const uint32_t*)(a1p);
                A[mf][2] = *(const uint32_t*)(a0p + 16);
                A[mf][3] = *(const uint32_t*)(a1p + 16);
            }
            const uint2* bp = (const uint2*)(smem + SM_B + buf * B_BYTES + kc * 4096)
                              + cq * 128 + lane;
            uint2 B[4];
#pragma unroll
            for (int nf = 0; nf < 4; ++nf) B[nf] = bp[nf * 32];
#pragma unroll
            for (int mf = 0; mf < 2; ++mf)
#pragma unroll
                for (int nf = 0; nf < 4; ++nf)
                    mma16816h(acc[nf][mf], A[mf][0], A[mf][1], A[mf][2], A[mf][3],
                              B[nf].x, B[nf].y);
        }

        // ---- approx argmin epilogue with second-best value tracking
#pragma unroll
        for (int nf = 0; nf < 4; ++nf) {
            int cb = t * NTILE + cq * 32 + nf * 8 + 2 * c;
            float e0 = esq_s[cb], e1 = esq_s[cb + 1];
#pragma unroll
            for (int mf = 0; mf < 2; ++mf) {
                float k00 = fmaf(-2.f, acc[nf][mf][0], __fadd_rn(ysr[mf][0], e0));
                float k01 = fmaf(-2.f, acc[nf][mf][1], __fadd_rn(ysr[mf][0], e1));
                float k10 = fmaf(-2.f, acc[nf][mf][2], __fadd_rn(ysr[mf][1], e0));
                float k11 = fmaf(-2.f, acc[nf][mf][3], __fadd_rn(ysr[mf][1], e1));
                upd(k00, cb,     v1[mf][0], c1[mf][0], v2[mf][0]);
                upd(k01, cb + 1, v1[mf][0], c1[mf][0], v2[mf][0]);
                upd(k10, cb,     v1[mf][1], c1[mf][1], v2[mf][1]);
                upd(k11, cb + 1, v1[mf][1], c1[mf][1], v2[mf][1]);
            }
        }
        __syncthreads();
    }

    // ---- merge across the 4 lanes (c) sharing each row
#pragma unroll
    for (int off = 1; off <= 2; off <<= 1) {
#pragma unroll
        for (int mf = 0; mf < 2; ++mf)
#pragma unroll
            for (int h = 0; h < 2; ++h) {
                float ov1 = __shfl_xor_sync(0xffffffffu, v1[mf][h], off);
                int   oc1 = __shfl_xor_sync(0xffffffffu, c1[mf][h], off);
                float ov2 = __shfl_xor_sync(0xffffffffu, v2[mf][h], off);
                mrg(ov1, oc1, ov2, v1[mf][h], c1[mf][h], v2[mf][h]);
            }
    }
    // ---- publish per-quarter (v1,c1,v2), merge across quarters
    float* qv  = (float*)(smem + SM_MRG);          // [cq][row]
    float* qv2 = (float*)(smem + SM_MRG + 2048);
    int*   qc  = (int*)(smem + SM_MRG + 4096);
    if (c == 0) {
#pragma unroll
        for (int mf = 0; mf < 2; ++mf)
#pragma unroll
            for (int h = 0; h < 2; ++h) {
                int r = cq * 128 + wg * 32 + mf * 16 + h * 8 + g;
                qv[r] = v1[mf][h]; qv2[r] = v2[mf][h]; qc[r] = c1[mf][h];
            }
    }
    __syncthreads();
    int* list = (int*)(smem + SM_LIST);
    int* cnt  = (int*)(smem + SM_CNT);
    if (tid < ROWS_PER_CTA) {
        float V1 = qv[tid], V2 = qv2[tid];
        int C = qc[tid];
#pragma unroll
        for (int q = 1; q < 4; ++q) {
            float o1 = qv[q * 128 + tid], o2 = qv2[q * 128 + tid];
            int oc = qc[q * 128 + tid];
            float loser = fmaxf(V1, o1);
            V2 = fminf(fminf(V2, o2), loser);
            bool p = o1 < V1;
            V1 = p ? o1 : V1;
            C = p ? oc : C;
        }
        cidx[tid] = C;
        if (V2 - V1 < EPS) {           // ambiguous under approx error -> exact rescan
            int slot = atomicAdd(cnt, 1);
            list[slot] = tid;
        }
    }
    __syncthreads();

    // ---- exact fp32 rescan of flagged rows (reference rounding, tie->lowest)
    // COALESCED: E is d-major (E[d*K+k]); thread handles codes {tid, tid+512},
    // so every warp LDG reads one contiguous 128B line.
    const int nflag = *cnt;
    float* xrow = (float*)(smem + SM_XROW);
    float* wrv  = (float*)(smem + SM_WRED);
    int*   wrc  = (int*)(smem + SM_WRED + 64);
    for (int i = 0; i < nflag; ++i) {
        int r = list[i];
        if (tid < 16)
            ((float4*)xrow)[tid] = ((const float4*)(x + (rowbase + r) * D_DIM))[tid];
        __syncthreads();
        float ys = ys_sh[r];
        float bestv = 3.402823466e38f;
        int   bestc = 0;
#pragma unroll
        for (int kk = 0; kk < 2; ++kk) {
            int k = tid + kk * MTHREADS;           // lanes consecutive -> coalesced
            float dot = 0.f;
#pragma unroll
            for (int d = 0; d < D_DIM; ++d)
                dot = fmaf(xrow[d], E[d * K_DIM + k], dot);
            float key = fmaf(-2.f, dot, __fadd_rn(ys, esq_s[k]));
            if (key < bestv || (key == bestv && k < bestc)) { bestv = key; bestc = k; }
        }
#pragma unroll
        for (int off = 16; off >= 1; off >>= 1) {
            float ov = __shfl_xor_sync(0xffffffffu, bestv, off);
            int   oc = __shfl_xor_sync(0xffffffffu, bestc, off);
            if (ov < bestv || (ov == bestv && oc < bestc)) { bestv = ov; bestc = oc; }
        }
        if (lane == 0) { wrv[wid] = bestv; wrc[wid] = bestc; }
        __syncthreads();
        if (tid == 0) {
            float bv = wrv[0]; int bcn = wrc[0];
#pragma unroll
            for (int w = 1; w < 16; ++w) {
                float v = wrv[w]; int cc = wrc[w];
                if (v < bv || (v == bv && cc < bcn)) { bv = v; bcn = cc; }
            }
            cidx[r] = bcn;
        }
        __syncthreads();
    }

    // ---- gather output rows from transposed codebook
    float* og = out + rowbase * D_DIM;
#pragma unroll
    for (int it = 0; it < 4; ++it) {
        int i  = tid + it * MTHREADS;
        int r  = i >> 4;
        int d0 = (i & 15) << 2;
        *(float4*)(og + r * D_DIM + d0) = *(const float4*)(g_ET + cidx[r] * D_DIM + d0);
    }
}

extern "C" void kernel_launch(void* const* d_in, const int* in_sizes, int n_in,
                              void* d_out, int out_size) {
    const float* x = (const float*)d_in[0];
    const float* E = (const float*)d_in[1];
    float* out = (float*)d_out;
    int N = in_sizes[0] / D_DIM;  // 131072

    cudaFuncSetAttribute(vq_tc, cudaFuncAttributeMaxDynamicSharedMemorySize, SM_TOTAL);
    vq_prep<<<K_DIM / 8, PTHREADS>>>(E);
    vq_prep_b<<<(NTILES * 4 * 16 * 32) / PTHREADS, PTHREADS>>>(E);
    vq_tc<<<N / ROWS_PER_CTA, MTHREADS, SM_TOTAL>>>(x, E, out);
}

// round 15
// speedup vs baseline: 7.0903x; 1.4917x over previous
#include <cuda_runtime.h>
#include <cuda_fp16.h>
#include <cstdint>

// vaeVectorQuantizer: x[N=131072, D=64], E[D=64, K=1024]
// Single fp16-product approx GEMM (mma.sync.m16n8k16.f16) ranking + per-row
// (best, secondVal) gap test + exact fp32 coalesced rescan for gap < EPS.
// R14: 64-row CTAs @ 256 threads, occupancy 3 (was 1) to hide phase latency;
// all norms via compensated fp32 (no FP64); coalesced prep.

#define D_DIM 64
#define K_DIM 1024
#define ROWS_PER_CTA 64
#define NTILE 128
#define NTILES 8
#define MTHREADS 256
#define EPS 1e-2f

#define PADROW 144
#define SM_X     0                         // 64 * 144 = 9216
#define SM_B     9216
#define B_BYTES  (NTILE * 64 * 2)          // 16384 per tile (fragment-packed h1)
#define SM_ESQ   (SM_B + 2 * B_BYTES)      // 41984
#define SM_YS    (SM_ESQ + 4096)           // 46080 (64 floats)
#define SM_MRG   (SM_YS + 256)             // 46336: qv[4][64], qv2[4][64], qc[4][64]
#define SM_CIDX  (SM_MRG + 3072)           // 49408 (64 ints)
#define SM_XROW  (SM_CIDX + 256)           // 49664 (one x row, 256B)
#define SM_LIST  (SM_XROW + 256)           // 49920 (64 ints)
#define SM_CNT   (SM_LIST + 256)           // 50176
#define SM_WRED  (SM_CNT + 16)             // 50192: 8*(float+int)=64
#define SM_TOTAL 50304

__device__ float g_esq[K_DIM];
__device__ float g_ET[K_DIM * D_DIM];          // [k][d] fp32: gather table
__device__ uint2 g_Bf[NTILES * 4 * 16 * 32];   // [t][kc][nf][lane] h1 fragments

__device__ __forceinline__ uint32_t smem_u32(const void* p) {
    uint32_t a;
    asm("{ .reg .u64 t; cvta.to.shared.u64 t, %1; cvt.u32.u64 %0, t; }" : "=r"(a) : "l"(p));
    return a;
}
__device__ __forceinline__ void cp16(uint32_t dst, const void* src) {
    asm volatile("cp.async.cg.shared.global [%0], [%1], 16;" :: "r"(dst), "l"(src));
}
#define CP_COMMIT() asm volatile("cp.async.commit_group;" ::: "memory")
#define CP_WAIT(N)  asm volatile("cp.async.wait_group %0;" :: "n"(N) : "memory")

__device__ __forceinline__ void mma16816h(float* c, uint32_t a0, uint32_t a1,
                                          uint32_t a2, uint32_t a3,
                                          uint32_t b0, uint32_t b1) {
    asm volatile(
        "mma.sync.aligned.m16n8k16.row.col.f32.f16.f16.f32 "
        "{%0,%1,%2,%3}, {%4,%5,%6,%7}, {%8,%9}, {%0,%1,%2,%3};"
        : "+f"(c[0]), "+f"(c[1]), "+f"(c[2]), "+f"(c[3])
        : "r"(a0), "r"(a1), "r"(a2), "r"(a3), "r"(b0), "r"(b1));
}

// compensated accumulate of v*v into (s, comp): exact product + Knuth 2Sum
__device__ __forceinline__ void csq(float v, float& s, float& comp) {
    float p = v * v;
    float e = fmaf(v, v, -p);
    float hi = s + p;
    float bb = hi - s;
    float err = (s - (hi - bb)) + (p - bb);
    s = hi;
    comp += err + e;
}
__device__ __forceinline__ void cmerge(float os, float ocmp, float& s, float& comp) {
    float hi = s + os;
    float bb = hi - s;
    float err = (s - (hi - bb)) + (os - bb);
    s = hi;
    comp += ocmp + err;
}

// approx top-1 + second-best value
__device__ __forceinline__ void upd(float k, int cb, float& v1, int& c1, float& v2) {
    bool p = k < v1;
    v2 = p ? v1 : fminf(v2, k);
    c1 = p ? cb : c1;
    v1 = p ? k : v1;
}
__device__ __forceinline__ void mrg(float ov1, int oc1, float ov2,
                                    float& v1, int& c1, float& v2) {
    float loser = fmaxf(v1, ov1);
    v2 = fminf(fminf(v2, ov2), loser);
    bool p = ov1 < v1;
    v1 = p ? ov1 : v1;
    c1 = p ? oc1 : c1;
}

// ---------------- prep: coalesced e_sq + transposed gather table ----------------
// 32 CTAs x 256 threads; CTA handles 32 codes via smem-tiled transpose.
__global__ void vq_prep(const float* __restrict__ E) {
    __shared__ float T[64][33];
    const int tid = threadIdx.x, lane = tid & 31, w = tid >> 5;
    const int k0 = blockIdx.x * 32;
#pragma unroll
    for (int dd = 0; dd < 8; ++dd) {
        int d = w * 8 + dd;
        T[d][lane] = E[d * K_DIM + k0 + lane];   // one 128B line per warp LDG
    }
    __syncthreads();
    const int k = tid >> 3;            // 0..31 (8 threads per code)
    const int dseg = (tid & 7) * 8;
    float s = 0.f, comp = 0.f;
#pragma unroll
    for (int j = 0; j < 8; ++j) csq(T[dseg + j][k], s, comp);
#pragma unroll
    for (int off = 1; off <= 4; off <<= 1) {
        float os   = __shfl_xor_sync(0xffffffffu, s, off);
        float ocmp = __shfl_xor_sync(0xffffffffu, comp, off);
        cmerge(os, ocmp, s, comp);
    }
    if ((tid & 7) == 0) g_esq[k0 + k] = s + comp;
    // transpose out: 8 consecutive d per thread -> two float4 stores
    float4 a, b;
    a.x = T[dseg + 0][k]; a.y = T[dseg + 1][k]; a.z = T[dseg + 2][k]; a.w = T[dseg + 3][k];
    b.x = T[dseg + 4][k]; b.y = T[dseg + 5][k]; b.z = T[dseg + 6][k]; b.w = T[dseg + 7][k];
    *(float4*)(g_ET + (k0 + k) * D_DIM + dseg)     = a;
    *(float4*)(g_ET + (k0 + k) * D_DIM + dseg + 4) = b;
}

// ---------------- prep: B h1 fragments in mma lane order ----------------
__global__ void vq_prep_b(const float* __restrict__ E) {
    int idx = blockIdx.x * blockDim.x + threadIdx.x;   // 16384 total
    int lane = idx & 31;
    int x1 = idx >> 5;
    int nf = x1 & 15;
    int x2 = x1 >> 4;
    int kc = x2 & 3;
    int t = x2 >> 2;

    int code = t * 128 + nf * 8 + (lane >> 2);
    int c = lane & 3;
    uint32_t r[2];
#pragma unroll
    for (int m = 0; m < 2; ++m) {
        int d0 = kc * 16 + c * 2 + m * 8;
        __half2 pk = __halves2half2(__float2half_rn(E[d0 * K_DIM + code]),
                                    __float2half_rn(E[(d0 + 1) * K_DIM + code]));
        r[m] = *(uint32_t*)&pk;
    }
    g_Bf[idx] = make_uint2(r[0], r[1]);
}

// ---------------- main ----------------
__global__ __launch_bounds__(MTHREADS, 3)
void vq_tc(const float* __restrict__ x, const float* __restrict__ E,
           float* __restrict__ out) {
    extern __shared__ __align__(16) char smem[];
    const int tid = threadIdx.x;
    const int wid = tid >> 5;
    const int lane = tid & 31;
    const size_t rowbase = (size_t)blockIdx.x * ROWS_PER_CTA;

    float* esq_s = (float*)(smem + SM_ESQ);
    float* ys_sh = (float*)(smem + SM_YS);
    int*   cidx  = (int*)(smem + SM_CIDX);
    const uint32_t sB_u32 = smem_u32(smem + SM_B);

    *(float4*)(esq_s + 4 * tid) = *(const float4*)(g_esq + 4 * tid);
    if (tid == 0) *(int*)(smem + SM_CNT) = 0;

    // ---- prefetch B tile 0
    {
        const char* src = (const char*)g_Bf;
#pragma unroll
        for (int i = 0; i < 4; ++i)
            cp16(sB_u32 + i * 4096 + tid * 16, src + i * 4096 + tid * 16);
        CP_COMMIT();
    }

    // ---- x: h1 fp16 into padded smem + compensated-fp32 row norms
    {
        int r = tid >> 2, dq = (tid & 3) * 16;
        const float* xr = x + (rowbase + r) * D_DIM + dq;
        char* xs = smem + SM_X + r * PADROW;
        float s = 0.f, comp = 0.f;
#pragma unroll
        for (int i = 0; i < 4; ++i) {
            float4 v = *(const float4*)(xr + 4 * i);
            int d0 = dq + 4 * i;
            csq(v.x, s, comp); csq(v.y, s, comp);
            csq(v.z, s, comp); csq(v.w, s, comp);
            *(__half2*)(xs + d0 * 2)     = __halves2half2(__float2half_rn(v.x), __float2half_rn(v.y));
            *(__half2*)(xs + d0 * 2 + 4) = __halves2half2(__float2half_rn(v.z), __float2half_rn(v.w));
        }
#pragma unroll
        for (int off = 1; off <= 2; off <<= 1) {
            float os   = __shfl_xor_sync(0xffffffffu, s, off);
            float ocmp = __shfl_xor_sync(0xffffffffu, comp, off);
            cmerge(os, ocmp, s, comp);
        }
        if ((tid & 3) == 0) ys_sh[r] = s + comp;
    }

    const int cq = wid >> 1;           // column quarter (32 codes)
    const int wg = wid & 1;            // row group (32 rows)
    const int g = lane >> 2, c = lane & 3;

    __syncthreads();

    float ysr[2][2];
    const char* aRow[2][2];
#pragma unroll
    for (int mf = 0; mf < 2; ++mf)
#pragma unroll
        for (int h = 0; h < 2; ++h) {
            int r = wg * 32 + mf * 16 + h * 8 + g;
            ysr[mf][h] = ys_sh[r];
            aRow[mf][h] = smem + SM_X + r * PADROW + c * 4;
        }

    float v1[2][2] = {{3.402823466e38f, 3.402823466e38f},
                      {3.402823466e38f, 3.402823466e38f}};
    float v2[2][2] = {{3.402823466e38f, 3.402823466e38f},
                      {3.402823466e38f, 3.402823466e38f}};
    int   c1[2][2] = {{0, 0}, {0, 0}};

    for (int t = 0; t < NTILES; ++t) {
        const int buf = t & 1;
        if (t + 1 < NTILES) {
            const char* src = (const char*)g_Bf + (t + 1) * B_BYTES;
            uint32_t dst = sB_u32 + (buf ^ 1) * B_BYTES;
#pragma unroll
            for (int i = 0; i < 4; ++i)
                cp16(dst + i * 4096 + tid * 16, src + i * 4096 + tid * 16);
            CP_COMMIT();
            CP_WAIT(1);
        } else {
            CP_WAIT(0);
        }
        __syncthreads();

        float acc[4][2][4];
#pragma unroll
        for (int nf = 0; nf < 4; ++nf)
#pragma unroll
            for (int mf = 0; mf < 2; ++mf)
#pragma unroll
                for (int j = 0; j < 4; ++j) acc[nf][mf][j] = 0.f;

#pragma unroll
        for (int kc = 0; kc < 4; ++kc) {
            uint32_t A[2][4];
#pragma unroll
            for (int mf = 0; mf < 2; ++mf) {
                const char* a0p = aRow[mf][0] + kc * 32;
                const char* a1p = aRow[mf][1] + kc * 32;
                A[mf][0] = *(const uint32_t*)(a0p);
                A[mf][1] = *(const uint32_t*)(a1p);
                A[mf][2] = *(const uint32_t*)(a0p + 16);
                A[mf][3] = *(const uint32_t*)(a1p + 16);
            }
            const uint2* bp = (const uint2*)(smem + SM_B + buf * B_BYTES + kc * 4096)
                              + cq * 128 + lane;
            uint2 B[4];
#pragma unroll
            for (int nf = 0; nf < 4; ++nf) B[nf] = bp[nf * 32];
#pragma unroll
            for (int mf = 0; mf < 2; ++mf)
#pragma unroll
                for (int nf = 0; nf < 4; ++nf)
                    mma16816h(acc[nf][mf], A[mf][0], A[mf][1], A[mf][2], A[mf][3],
                              B[nf].x, B[nf].y);
        }

        // ---- approx argmin epilogue with second-best value tracking
#pragma unroll
        for (int nf = 0; nf < 4; ++nf) {
            int cb = t * NTILE + cq * 32 + nf * 8 + 2 * c;
            float e0 = esq_s[cb], e1 = esq_s[cb + 1];
#pragma unroll
            for (int mf = 0; mf < 2; ++mf) {
                float k00 = fmaf(-2.f, acc[nf][mf][0], __fadd_rn(ysr[mf][0], e0));
                float k01 = fmaf(-2.f, acc[nf][mf][1], __fadd_rn(ysr[mf][0], e1));
                float k10 = fmaf(-2.f, acc[nf][mf][2], __fadd_rn(ysr[mf][1], e0));
                float k11 = fmaf(-2.f, acc[nf][mf][3], __fadd_rn(ysr[mf][1], e1));
                upd(k00, cb,     v1[mf][0], c1[mf][0], v2[mf][0]);
                upd(k01, cb + 1, v1[mf][0], c1[mf][0], v2[mf][0]);
                upd(k10, cb,     v1[mf][1], c1[mf][1], v2[mf][1]);
                upd(k11, cb + 1, v1[mf][1], c1[mf][1], v2[mf][1]);
            }
        }
        __syncthreads();
    }

    // ---- merge across the 4 lanes (c) sharing each row
#pragma unroll
    for (int off = 1; off <= 2; off <<= 1) {
#pragma unroll
        for (int mf = 0; mf < 2; ++mf)
#pragma unroll
            for (int h = 0; h < 2; ++h) {
                float ov1 = __shfl_xor_sync(0xffffffffu, v1[mf][h], off);
                int   oc1 = __shfl_xor_sync(0xffffffffu, c1[mf][h], off);
                float ov2 = __shfl_xor_sync(0xffffffffu, v2[mf][h], off);
                mrg(ov1, oc1, ov2, v1[mf][h], c1[mf][h], v2[mf][h]);
            }
    }
    // ---- publish per-quarter (v1,c1,v2), merge across quarters
    float* qv  = (float*)(smem + SM_MRG);          // [cq][row]
    float* qv2 = (float*)(smem + SM_MRG + 1024);
    int*   qc  = (int*)(smem + SM_MRG + 2048);
    if (c == 0) {
#pragma unroll
        for (int mf = 0; mf < 2; ++mf)
#pragma unroll
            for (int h = 0; h < 2; ++h) {
                int r = cq * 64 + wg * 32 + mf * 16 + h * 8 + g;
                qv[r] = v1[mf][h]; qv2[r] = v2[mf][h]; qc[r] = c1[mf][h];
            }
    }
    __syncthreads();
    int* list = (int*)(smem + SM_LIST);
    int* cnt  = (int*)(smem + SM_CNT);
    if (tid < ROWS_PER_CTA) {
        float V1 = qv[tid], V2 = qv2[tid];
        int C = qc[tid];
#pragma unroll
        for (int q = 1; q < 4; ++q) {
            float o1 = qv[q * 64 + tid], o2 = qv2[q * 64 + tid];
            int oc = qc[q * 64 + tid];
            float loser = fmaxf(V1, o1);
            V2 = fminf(fminf(V2, o2), loser);
            bool p = o1 < V1;
            V1 = p ? o1 : V1;
            C = p ? oc : C;
        }
        cidx[tid] = C;
        if (V2 - V1 < EPS) {
            int slot = atomicAdd(cnt, 1);
            list[slot] = tid;
        }
    }
    __syncthreads();

    // ---- exact fp32 rescan of flagged rows (reference rounding, tie->lowest)
    // E is d-major: thread handles codes {tid + kk*256}, lanes consecutive ->
    // every warp LDG is one 128B line.
    const int nflag = *cnt;
    float* xrow = (float*)(smem + SM_XROW);
    float* wrv  = (float*)(smem + SM_WRED);
    int*   wrc  = (int*)(smem + SM_WRED + 32);
    for (int i = 0; i < nflag; ++i) {
        int r = list[i];
        if (tid < 16)
            ((float4*)xrow)[tid] = ((const float4*)(x + (rowbase + r) * D_DIM))[tid];
        __syncthreads();
        float ys = ys_sh[r];
        float dot[4] = {0.f, 0.f, 0.f, 0.f};
#pragma unroll
        for (int d = 0; d < D_DIM; ++d) {
            float xv = xrow[d];
            const float* Ed = E + d * K_DIM + tid;
#pragma unroll
            for (int kk = 0; kk < 4; ++kk)
                dot[kk] = fmaf(xv, Ed[kk * MTHREADS], dot[kk]);
        }
        float bestv = 3.402823466e38f;
        int   bestc = 0;
#pragma unroll
        for (int kk = 0; kk < 4; ++kk) {
            int k = tid + kk * MTHREADS;
            float key = fmaf(-2.f, dot[kk], __fadd_rn(ys, esq_s[k]));
            if (key < bestv || (key == bestv && k < bestc)) { bestv = key; bestc = k; }
        }
#pragma unroll
        for (int off = 16; off >= 1; off >>= 1) {
            float ov = __shfl_xor_sync(0xffffffffu, bestv, off);
            int   oc = __shfl_xor_sync(0xffffffffu, bestc, off);
            if (ov < bestv || (ov == bestv && oc < bestc)) { bestv = ov; bestc = oc; }
        }
        if (lane == 0) { wrv[wid] = bestv; wrc[wid] = bestc; }
        __syncthreads();
        if (tid == 0) {
            float bv = wrv[0]; int bcn = wrc[0];
#pragma unroll
            for (int w = 1; w < 8; ++w) {
                float v = wrv[w]; int cc = wrc[w];
                if (v < bv || (v == bv && cc < bcn)) { bv = v; bcn = cc; }
            }
            cidx[r] = bcn;
        }
        __syncthreads();
    }

    // ---- gather output rows from transposed codebook
    float* og = out + rowbase * D_DIM;
#pragma unroll
    for (int it = 0; it < 4; ++it) {
        int i  = tid + it * MTHREADS;   // 0..1023 = 64 rows x 16 float4
        int r  = i >> 4;
        int d0 = (i & 15) << 2;
        *(float4*)(og + r * D_DIM + d0) = *(const float4*)(g_ET + cidx[r] * D_DIM + d0);
    }
}

extern "C" void kernel_launch(void* const* d_in, const int* in_sizes, int n_in,
                              void* d_out, int out_size) {
    const float* x = (const float*)d_in[0];
    const float* E = (const float*)d_in[1];
    float* out = (float*)d_out;
    int N = in_sizes[0] / D_DIM;  // 131072

    cudaFuncSetAttribute(vq_tc, cudaFuncAttributeMaxDynamicSharedMemorySize, SM_TOTAL);
    vq_prep<<<K_DIM / 32, MTHREADS>>>(E);
    vq_prep_b<<<(NTILES * 4 * 16 * 32) / MTHREADS, MTHREADS>>>(E);
    vq_tc<<<N / ROWS_PER_CTA, MTHREADS, SM_TOTAL>>>(x, E, out);
}